// round 1
// baseline (speedup 1.0000x reference)
#include <cuda_runtime.h>
#include <math.h>

// ---------------------------------------------------------------------------
// Encoder_conv2: 5-level grid encoder.
//   per level: a = tanh(depthwise_conv3x3(F));  out_l = sum_{cell} bilinear(a[cell], p + 0.5*cell)
// Trick: sum of the 2 cell-samples (cell offset = +0.5 px diagonal) is piecewise
// bilinear on the half-integer lattice -> precompute merged grid G[(2r)^2][4ch],
// main kernel does a single bilinear fetch per level.
// ---------------------------------------------------------------------------

static __device__ __constant__ const int d_dummy = 0; // keep nvcc happy about empty const seg

#define NLEV 5
__device__ static const int RESA_[NLEV] = {8, 12, 20, 18, 32};

// a texels cumulative: 2*r*r per level
#define ATEX0 0
#define ATEX1 128
#define ATEX2 416
#define ATEX3 1216
#define ATEX4 1864
#define ATEXT 3912
// G texels cumulative: (2r)^2 per level
#define GTEX0 0
#define GTEX1 256
#define GTEX2 832
#define GTEX3 2432
#define GTEX4 3728
#define GTEXT 7824

#define SMEM_BYTES (GTEXT * 16)

__device__ float4 g_a4[ATEXT];   // [level][cell][y][x] -> 4 channels
__device__ float4 g_G[GTEXT];    // [level][ky][kx] on half-int lattice -> 4 channels

// ---------------------------------------------------------------------------
// Kernel 1: depthwise conv3x3 (SAME, zero pad, cross-correlation) + tanh.
// One thread per texel (cell,y,x), computes all 4 channels.
// ---------------------------------------------------------------------------
__global__ void k_conv(const float* __restrict__ F0, const float* __restrict__ F1,
                       const float* __restrict__ F2, const float* __restrict__ F3,
                       const float* __restrict__ F4, const float* __restrict__ W) {
    int tex = blockIdx.x * blockDim.x + threadIdx.x;
    if (tex >= ATEXT) return;

    const int acum[6] = {ATEX0, ATEX1, ATEX2, ATEX3, ATEX4, ATEXT};
    int l = 0;
    #pragma unroll
    for (int q = 0; q < 4; q++) if (tex >= acum[q + 1]) l = q + 1;

    const float* Fl = (l == 0) ? F0 : (l == 1) ? F1 : (l == 2) ? F2 : (l == 3) ? F3 : F4;
    const int r = RESA_[l];
    int rem = tex - acum[l];
    int rr  = r * r;
    int j   = rem / rr;
    int yx  = rem - j * rr;
    int y   = yx / r;
    int x   = yx - y * r;

    float oc[4];
    #pragma unroll
    for (int c = 0; c < 4; c++) {
        float s = 0.f;
        for (int dy = 0; dy < 3; dy++) {
            int yy = y + dy - 1;
            if (yy < 0 || yy >= r) continue;
            for (int dx = 0; dx < 3; dx++) {
                int xx = x + dx - 1;
                if (xx < 0 || xx >= r) continue;
                s += Fl[((j * 4 + c) * r + yy) * r + xx] * W[c * 9 + dy * 3 + dx];
            }
        }
        oc[c] = tanhf(s);
    }
    g_a4[tex] = make_float4(oc[0], oc[1], oc[2], oc[3]);
}

// ---------------------------------------------------------------------------
// Kernel 2: build merged half-lattice node grid.
// G[k][m] = sum_{cell j} bilinear_with_clamp(a[j], px=(m+j)/2, py=(k+j)/2)
// ---------------------------------------------------------------------------
__global__ void k_nodes() {
    int tex = blockIdx.x * blockDim.x + threadIdx.x;
    if (tex >= GTEXT) return;

    const int gcum[6] = {GTEX0, GTEX1, GTEX2, GTEX3, GTEX4, GTEXT};
    const int acum[5] = {ATEX0, ATEX1, ATEX2, ATEX3, ATEX4};
    int l = 0;
    #pragma unroll
    for (int q = 0; q < 4; q++) if (tex >= gcum[q + 1]) l = q + 1;

    const int r  = RESA_[l];
    const int n2 = 2 * r;
    int rem = tex - gcum[l];
    int k   = rem / n2;
    int m   = rem - k * n2;

    float ax = 0.f, ay = 0.f, az = 0.f, aw = 0.f;
    #pragma unroll
    for (int j = 0; j < 2; j++) {
        float px = 0.5f * (float)(m + j);
        float py = 0.5f * (float)(k + j);
        float fx = floorf(px), fy = floorf(py);
        float wx = px - fx,    wy = py - fy;
        int ix0 = (int)fx, iy0 = (int)fy;
        int x0 = min(max(ix0,     0), r - 1);
        int x1 = min(max(ix0 + 1, 0), r - 1);
        int y0 = min(max(iy0,     0), r - 1);
        int y1 = min(max(iy0 + 1, 0), r - 1);
        int base = acum[l] + j * r * r;
        float4 c00 = g_a4[base + y0 * r + x0];
        float4 c01 = g_a4[base + y0 * r + x1];
        float4 c10 = g_a4[base + y1 * r + x0];
        float4 c11 = g_a4[base + y1 * r + x1];
        float w00 = (1.f - wx) * (1.f - wy);
        float w01 = wx * (1.f - wy);
        float w10 = (1.f - wx) * wy;
        float w11 = wx * wy;
        ax += c00.x * w00 + c01.x * w01 + c10.x * w10 + c11.x * w11;
        ay += c00.y * w00 + c01.y * w01 + c10.y * w10 + c11.y * w11;
        az += c00.z * w00 + c01.z * w01 + c10.z * w10 + c11.z * w11;
        aw += c00.w * w00 + c01.w * w01 + c10.w * w10 + c11.w * w11;
    }
    g_G[tex] = make_float4(ax, ay, az, aw);
}

// ---------------------------------------------------------------------------
// Kernel 3: per-point sampling. Grids staged in dynamic smem (122 KB).
// One bilinear fetch (4 float4 LDS) per level per point; 5 float4 stores/point.
// ---------------------------------------------------------------------------
__global__ void __launch_bounds__(512, 1)
k_sample(const float* __restrict__ X, const float* __restrict__ Y,
         float* __restrict__ out, int npts) {
    extern __shared__ float4 sg[];
    for (int i = threadIdx.x; i < GTEXT; i += blockDim.x) sg[i] = g_G[i];
    __syncthreads();

    const int gbase[5] = {GTEX0, GTEX1, GTEX2, GTEX3, GTEX4};
    const int resa [5] = {8, 12, 20, 18, 32};

    int stride = gridDim.x * blockDim.x;
    for (int p = blockIdx.x * blockDim.x + threadIdx.x; p < npts; p += stride) {
        // replicate reference coordinate math: gx = x*2-1; ix=(gx+1)*0.5*(r-1)
        float tx = X[p] * 2.f - 1.f;
        float ty = Y[p] * 2.f - 1.f;
        float hx = (tx + 1.f) * 0.5f;   // in [0,1)
        float hy = (ty + 1.f) * 0.5f;

        float4 res[5];
        #pragma unroll
        for (int l = 0; l < 5; l++) {
            const int r  = resa[l];
            const int n2 = 2 * r;
            // doubled coordinate on the half-integer lattice: h = 2*ix
            float h = hx * (float)(2 * r - 2);
            float v = hy * (float)(2 * r - 2);
            float fh = floorf(h), fv = floorf(v);
            int m0 = (int)fh;
            int k0 = (int)fv;
            m0 = min(max(m0, 0), n2 - 2);
            k0 = min(max(k0, 0), n2 - 2);
            float wx = h - (float)m0;
            float wy = v - (float)k0;

            const float4* row0 = sg + gbase[l] + k0 * n2 + m0;
            const float4* row1 = row0 + n2;
            float4 c00 = row0[0];
            float4 c01 = row0[1];
            float4 c10 = row1[0];
            float4 c11 = row1[1];

            float w00 = (1.f - wx) * (1.f - wy);
            float w01 = wx * (1.f - wy);
            float w10 = (1.f - wx) * wy;
            float w11 = wx * wy;

            float4 o;
            o.x = c00.x * w00 + c01.x * w01 + c10.x * w10 + c11.x * w11;
            o.y = c00.y * w00 + c01.y * w01 + c10.y * w10 + c11.y * w11;
            o.z = c00.z * w00 + c01.z * w01 + c10.z * w10 + c11.z * w11;
            o.w = c00.w * w00 + c01.w * w01 + c10.w * w10 + c11.w * w11;
            res[l] = o;
        }

        float4* op = reinterpret_cast<float4*>(out + (size_t)p * 20);
        #pragma unroll
        for (int l = 0; l < 5; l++) op[l] = res[l];
    }
}

// ---------------------------------------------------------------------------
extern "C" void kernel_launch(void* const* d_in, const int* in_sizes, int n_in,
                              void* d_out, int out_size) {
    const float* X = nullptr;
    const float* Yv = nullptr;
    const float* W = nullptr;
    const float* F[5] = {nullptr, nullptr, nullptr, nullptr, nullptr};
    int npts = 0;

    for (int i = 0; i < n_in; i++) {
        int s = in_sizes[i];
        const float* p = (const float*)d_in[i];
        if (s == 36)        W   = p;
        else if (s == 512)  F[0] = p;
        else if (s == 1152) F[1] = p;
        else if (s == 3200) F[2] = p;
        else if (s == 2592) F[3] = p;
        else if (s == 8192) F[4] = p;
        else {
            if (!X) { X = p; npts = s; }
            else     Yv = p;
        }
    }

    k_conv<<<(ATEXT + 255) / 256, 256>>>(F[0], F[1], F[2], F[3], F[4], W);
    k_nodes<<<(GTEXT + 255) / 256, 256>>>();

    cudaFuncSetAttribute(k_sample, cudaFuncAttributeMaxDynamicSharedMemorySize, SMEM_BYTES);
    k_sample<<<152, 512, SMEM_BYTES>>>(X, Yv, (float*)d_out, npts);
}